// round 14
// baseline (speedup 1.0000x reference)
#include <cuda_runtime.h>
#include <cuda_bf16.h>
#include <math.h>
#include <stdint.h>

#define LQ 256
#define BQ 64
#define DQ 1024
#define VQ 32000
#define MQ (LQ * BQ)          // 16384 rows for projections
#define NB_SCAN 128

// ---------------- scratch (static device globals; no allocation) ----------------
__device__ float g_x [LQ * BQ * DQ];   // current layer input / bw output
__device__ float g_h [LQ * BQ * DQ];   // fw output ("first")
__device__ float g_xi[LQ * BQ * DQ];
__device__ float g_xf[LQ * BQ * DQ];
__device__ float g_xc[LQ * BQ * DQ];
__device__ float g_chand[BQ * DQ];               // fp32 c handoff between scans
__device__ __nv_bfloat16 g_cbf[2 * BQ * DQ];     // bf16 shadow of c for mma loads
__device__ __nv_bfloat16 g_abh[LQ * BQ * DQ];    // GEMM A operand bf16 hi
__device__ __nv_bfloat16 g_abl[LQ * BQ * DQ];    // GEMM A operand bf16 lo
__device__ __nv_bfloat16 g_wth[6 * DQ * DQ];     // weights transposed [N][K] bf16 hi
__device__ __nv_bfloat16 g_wtl[6 * DQ * DQ];     // weights transposed [N][K] bf16 lo
__device__ unsigned g_flags[NB_SCAN + 1];        // per-CTA arrival flags + go word

// ---------------- embedding gather ----------------
__global__ __launch_bounds__(256) void embed_kernel(
    const int* __restrict__ xs, const float* __restrict__ emb, float* __restrict__ x)
{
    int i = blockIdx.x * 256 + threadIdx.x;     // over MQ*DQ/4 float4's
    int tokpos = i >> 8;                        // DQ/4 = 256 float4 per row
    int d4 = i & 255;
    int tok = xs[tokpos];
    tok = min(max(tok, 0), VQ - 1);
    ((float4*)x)[i] = ((const float4*)(emb + (size_t)tok * DQ))[d4];
}

__global__ __launch_bounds__(256) void zero_kernel(float* __restrict__ p, int n)
{
    int i = blockIdx.x * 256 + threadIdx.x;
    if (i < n) p[i] = 0.0f;
}

// ---------------- mma helpers ----------------
__device__ __forceinline__ void mma_bf16(float d[4],
    uint32_t a0, uint32_t a1, uint32_t a2, uint32_t a3,
    uint32_t b0, uint32_t b1)
{
    asm volatile(
        "mma.sync.aligned.m16n8k16.row.col.f32.bf16.bf16.f32 "
        "{%0,%1,%2,%3}, {%4,%5,%6,%7}, {%8,%9}, {%0,%1,%2,%3};"
        : "+f"(d[0]), "+f"(d[1]), "+f"(d[2]), "+f"(d[3])
        : "r"(a0), "r"(a1), "r"(a2), "r"(a3), "r"(b0), "r"(b1));
}

__device__ __forceinline__ uint32_t pack_bf16x2(float lo, float hi)
{
    __nv_bfloat162 p = __floats2bfloat162_rn(lo, hi);
    return *reinterpret_cast<uint32_t*>(&p);
}

__device__ __forceinline__ void split_bf16(float v, __nv_bfloat16& h, __nv_bfloat16& l)
{
    h = __float2bfloat16_rn(v);
    l = __float2bfloat16_rn(v - __bfloat162float(h));
}

// ---------------- A split kernel: fp32 -> bf16 hi/lo (row-major) --------------
__global__ __launch_bounds__(256) void asplit_kernel(
    const float4* __restrict__ src, uint2* __restrict__ hi, uint2* __restrict__ lo, int n4)
{
    int i = blockIdx.x * 256 + threadIdx.x;
    if (i >= n4) return;
    float4 v = src[i];
    __nv_bfloat16 hx, lx, hy, ly, hz, lz, hw, lw;
    split_bf16(v.x, hx, lx);
    split_bf16(v.y, hy, ly);
    split_bf16(v.z, hz, lz);
    split_bf16(v.w, hw, lw);
    uint2 hv, lv;
    hv.x = pack_bf16x2(__bfloat162float(hx), __bfloat162float(hy));
    hv.y = pack_bf16x2(__bfloat162float(hz), __bfloat162float(hw));
    lv.x = pack_bf16x2(__bfloat162float(lx), __bfloat162float(ly));
    lv.y = pack_bf16x2(__bfloat162float(lz), __bfloat162float(lw));
    hi[i] = hv;
    lo[i] = lv;
}

// ---------------- W transpose+split kernel: W[K][N] fp32 -> Wt[N][K] bf16 hi/lo
__global__ void wsplit_t_kernel(const float* __restrict__ W,
                                __nv_bfloat16* __restrict__ Th,
                                __nv_bfloat16* __restrict__ Tl)
{
    __shared__ float tile[32][33];
    int tx = threadIdx.x, ty = threadIdx.y;     // 32 x 8
    int n0 = blockIdx.x * 32, k0 = blockIdx.y * 32;
    #pragma unroll
    for (int i = 0; i < 32; i += 8)
        tile[ty + i][tx] = W[(size_t)(k0 + ty + i) * DQ + n0 + tx];
    __syncthreads();
    #pragma unroll
    for (int i = 0; i < 32; i += 8) {
        float v = tile[tx][ty + i];             // = W[k0+tx][n0+ty+i]
        __nv_bfloat16 h, l;
        split_bf16(v, h, l);
        size_t o = (size_t)(n0 + ty + i) * DQ + k0 + tx;
        Th[o] = h;
        Tl[o] = l;
    }
}

// ---------------- 2xBF16 tensor-core GEMM + bias: C = A@W + bias --------------
#define TBM 128
#define TBN 128
#define TBK 16
#define BFPAD 8                        // bf16 pad -> stride 24 (conflict-free)
#define BF_STRIDE (TBK + BFPAD)        // 24 bf16
#define BF_TILE (128 * BF_STRIDE)      // 3072 bf16 per buf (A and B same shape)
#define OFF_ABH 0
#define OFF_ABL (2 * BF_TILE)
#define OFF_BBH (4 * BF_TILE)
#define OFF_BBL (6 * BF_TILE)
#define GEMM_SMEM_BYTES (8 * BF_TILE * 2)   // 49152

__global__ __launch_bounds__(256) void sgemm_bf16x2(
    const __nv_bfloat16* __restrict__ Ahi, const __nv_bfloat16* __restrict__ Alo,
    const __nv_bfloat16* __restrict__ Wth, const __nv_bfloat16* __restrict__ Wtl,
    const float* __restrict__ bias, float* __restrict__ C)
{
    extern __shared__ __align__(16) __nv_bfloat16 smb[];

    const int tid  = threadIdx.x;
    const int lane = tid & 31;
    const int w    = tid >> 5;
    const int gid  = lane >> 2;
    const int tig  = lane & 3;
    const int wm0  = (w >> 2) * 64;   // warp m offset in tile
    const int wn0  = (w & 3) * 32;    // warp n offset in tile
    const int m0   = blockIdx.y * TBM;
    const int n0   = blockIdx.x * TBN;

    float acc[4][4][4];
    #pragma unroll
    for (int mf = 0; mf < 4; mf++)
        #pragma unroll
        for (int nf = 0; nf < 4; nf++)
            #pragma unroll
            for (int r = 0; r < 4; r++) acc[mf][nf][r] = 0.f;

    auto load_tiles = [&](int it, int buf) {
        int k0 = it * TBK;
        int row = tid >> 1, seg = tid & 1;
        {
            size_t goff = (size_t)(m0 + row) * DQ + k0 + seg * 8;
            int soff = buf * BF_TILE + row * BF_STRIDE + seg * 8;
            uint32_t d0 = (uint32_t)__cvta_generic_to_shared(&smb[OFF_ABH + soff]);
            uint32_t d1 = (uint32_t)__cvta_generic_to_shared(&smb[OFF_ABL + soff]);
            asm volatile("cp.async.ca.shared.global [%0], [%1], 16;" :: "r"(d0), "l"(Ahi + goff));
            asm volatile("cp.async.ca.shared.global [%0], [%1], 16;" :: "r"(d1), "l"(Alo + goff));
        }
        {
            size_t goff = (size_t)(n0 + row) * DQ + k0 + seg * 8;
            int soff = buf * BF_TILE + row * BF_STRIDE + seg * 8;
            uint32_t d0 = (uint32_t)__cvta_generic_to_shared(&smb[OFF_BBH + soff]);
            uint32_t d1 = (uint32_t)__cvta_generic_to_shared(&smb[OFF_BBL + soff]);
            asm volatile("cp.async.ca.shared.global [%0], [%1], 16;" :: "r"(d0), "l"(Wth + goff));
            asm volatile("cp.async.ca.shared.global [%0], [%1], 16;" :: "r"(d1), "l"(Wtl + goff));
        }
        asm volatile("cp.async.commit_group;");
    };

    load_tiles(0, 0);

    const int NIT = DQ / TBK;   // 64
    for (int it = 0; it < NIT; it++) {
        int buf = it & 1;
        if (it + 1 < NIT) {
            load_tiles(it + 1, buf ^ 1);
            asm volatile("cp.async.wait_group 1;");
        } else {
            asm volatile("cp.async.wait_group 0;");
        }
        __syncthreads();

        uint32_t ah[4][4], al[4][4];
        #pragma unroll
        for (int mf = 0; mf < 4; mf++) {
            int r = wm0 + mf * 16;
            int i0 = buf * BF_TILE + (r + gid) * BF_STRIDE + 2 * tig;
            int i1 = buf * BF_TILE + (r + gid + 8) * BF_STRIDE + 2 * tig;
            ah[mf][0] = *(const uint32_t*)&smb[OFF_ABH + i0];
            ah[mf][1] = *(const uint32_t*)&smb[OFF_ABH + i1];
            ah[mf][2] = *(const uint32_t*)&smb[OFF_ABH + i0 + 8];
            ah[mf][3] = *(const uint32_t*)&smb[OFF_ABH + i1 + 8];
            al[mf][0] = *(const uint32_t*)&smb[OFF_ABL + i0];
            al[mf][1] = *(const uint32_t*)&smb[OFF_ABL + i1];
            al[mf][2] = *(const uint32_t*)&smb[OFF_ABL + i0 + 8];
            al[mf][3] = *(const uint32_t*)&smb[OFF_ABL + i1 + 8];
        }
        uint32_t bh[4][2], bl[4][2];
        #pragma unroll
        for (int nf = 0; nf < 4; nf++) {
            int cN = wn0 + nf * 8 + gid;
            int j0 = buf * BF_TILE + cN * BF_STRIDE + 2 * tig;
            bh[nf][0] = *(const uint32_t*)&smb[OFF_BBH + j0];
            bh[nf][1] = *(const uint32_t*)&smb[OFF_BBH + j0 + 8];
            bl[nf][0] = *(const uint32_t*)&smb[OFF_BBL + j0];
            bl[nf][1] = *(const uint32_t*)&smb[OFF_BBL + j0 + 8];
        }
        #pragma unroll
        for (int mf = 0; mf < 4; mf++)
            #pragma unroll
            for (int nf = 0; nf < 4; nf++) {
                mma_bf16(acc[mf][nf], ah[mf][0], ah[mf][1], ah[mf][2], ah[mf][3],
                         bh[nf][0], bh[nf][1]);
                mma_bf16(acc[mf][nf], al[mf][0], al[mf][1], al[mf][2], al[mf][3],
                         bh[nf][0], bh[nf][1]);
                mma_bf16(acc[mf][nf], ah[mf][0], ah[mf][1], ah[mf][2], ah[mf][3],
                         bl[nf][0], bl[nf][1]);
            }
        __syncthreads();
    }

    #pragma unroll
    for (int mf = 0; mf < 4; mf++) {
        #pragma unroll
        for (int nf = 0; nf < 4; nf++) {
            int r0 = m0 + wm0 + mf * 16 + gid;
            int cN = n0 + wn0 + nf * 8 + 2 * tig;
            float2 bv = *(const float2*)(bias + cN);
            float2 o0 = make_float2(acc[mf][nf][0] + bv.x, acc[mf][nf][1] + bv.y);
            float2 o1 = make_float2(acc[mf][nf][2] + bv.x, acc[mf][nf][3] + bv.y);
            *(float2*)(C + (size_t)r0 * DQ + cN) = o0;
            *(float2*)(C + (size_t)(r0 + 8) * DQ + cN) = o1;
        }
    }
}

// ---------------- persistent scan kernel (bf16 mma, register fp32 recurrence) --
// 128 CTAs x 256 threads; CTA owns 8 output columns. Serial chain per step is
// minimized: reduce -> c' -> bf16 shadow store -> arrive; the tanh/h-store and
// the NEXT step's operand prefetch execute in the barrier-wait shadow.
// SMEM: Bs 64 mma * 2 nf * 32 lanes * 8B = 32 KB, partials 32 KB
#define SCAN_SMEM_BYTES (32768 + 32768)

__global__ __launch_bounds__(256) void scan_kernel(
    const float* __restrict__ x,  const float* __restrict__ xi,
    const float* __restrict__ xf, const float* __restrict__ xc,
    const float* __restrict__ Wic, const float* __restrict__ Wfc,
    float* __restrict__ chand,             // [BQ*DQ] fp32 handoff
    __nv_bfloat16* __restrict__ cbf,       // [2][BQ*DQ] bf16 shadow
    float* __restrict__ h, int reverse, int epoch)
{
    extern __shared__ __align__(16) char smem_raw[];
    uint2* Bs   = (uint2*)smem_raw;                  // [64 mma][2 nf][32 lanes]
    float* part = (float*)(smem_raw + 32768);        // [8 warps][64 b][16 cols]

    const int tid  = threadIdx.x;
    const int lane = tid & 31;
    const int w    = tid >> 5;
    const int gid  = lane >> 2;       // groupID 0..7
    const int tig  = lane & 3;        // threadID in group
    const int n0   = blockIdx.x * 8;  // this CTA's output column base
    const int bid  = blockIdx.x;

    // ---- pre-lay weights bf16 in fragment order (once per scan) ----
    for (int idx = tid; idx < 64 * 2 * 32; idx += 256) {
        int l    = idx & 31;
        int nf   = (idx >> 5) & 1;
        int mi   = idx >> 6;
        int s    = mi >> 1;
        int half = mi & 1;
        int k0   = 32 * s + 8 * (l & 3) + 4 * half;
        int col  = n0 + (l >> 2);
        const float* M = nf ? Wfc : Wic;
        uint2 v;
        v.x = pack_bf16x2(M[(size_t)(k0 + 0) * DQ + col], M[(size_t)(k0 + 1) * DQ + col]);
        v.y = pack_bf16x2(M[(size_t)(k0 + 2) * DQ + col], M[(size_t)(k0 + 3) * DQ + col]);
        Bs[idx] = v;
    }
    __syncthreads();

    // tail addressing: 2 reps x 256 threads cover 64 b x 8 n cell updates;
    // fp32 c carried in registers across all steps.
    int bbs[2], gns[2];
    float t_c[2];
    size_t cboff[2];
    #pragma unroll
    for (int rep = 0; rep < 2; rep++) {
        int rr = tid + rep * 256;
        bbs[rep] = rr >> 3;
        gns[rep] = n0 + (rr & 7);
        cboff[rep] = (size_t)bbs[rep] * DQ + gns[rep];
        t_c[rep] = chand[cboff[rep]];   // initial c
    }

    // prefetch step-0 tail operands
    float t_xi[2], t_xf[2], t_xc[2], t_x[2];
    size_t offs[2];
    {
        const int t0 = reverse ? (LQ - 1) : 0;
        #pragma unroll
        for (int rep = 0; rep < 2; rep++) {
            size_t off = ((size_t)t0 * BQ + bbs[rep]) * DQ + gns[rep];
            offs[rep] = off;
            t_xi[rep] = __ldcg(xi + off);
            t_xf[rep] = __ldcg(xf + off);
            t_xc[rep] = __ldcg(xc + off);
            t_x[rep]  = __ldcg(x + off);
        }
    }

    for (int step = 0; step < LQ; step++) {
        const __nv_bfloat16* cbprev = cbf + (step & 1) * (BQ * DQ);
        __nv_bfloat16* cbnext = cbf + ((step + 1) & 1) * (BQ * DQ);

        float acc[4][2][4];
        #pragma unroll
        for (int m = 0; m < 4; m++)
            #pragma unroll
            for (int nf = 0; nf < 2; nf++)
                #pragma unroll
                for (int r = 0; r < 4; r++) acc[m][nf][r] = 0.f;

        #pragma unroll
        for (int j = 0; j < 4; j++) {
            int s = 4 * w + j;
            uint2 bu0 = Bs[((2 * s + 0) * 2 + 0) * 32 + lane];
            uint2 bv0 = Bs[((2 * s + 0) * 2 + 1) * 32 + lane];
            uint2 bu1 = Bs[((2 * s + 1) * 2 + 0) * 32 + lane];
            uint2 bv1 = Bs[((2 * s + 1) * 2 + 1) * 32 + lane];
            const __nv_bfloat16* abase = cbprev + (size_t)gid * DQ + 32 * s + 8 * tig;
            uint4 av[8];
            #pragma unroll
            for (int m = 0; m < 4; m++) {
                av[2 * m]     = __ldcg((const uint4*)(abase + (size_t)(m * 16) * DQ));
                av[2 * m + 1] = __ldcg((const uint4*)(abase + (size_t)(m * 16 + 8) * DQ));
            }
            #pragma unroll
            for (int m = 0; m < 4; m++) {
                mma_bf16(acc[m][0], av[2*m].x, av[2*m+1].x, av[2*m].y, av[2*m+1].y,
                         bu0.x, bu0.y);
                mma_bf16(acc[m][1], av[2*m].x, av[2*m+1].x, av[2*m].y, av[2*m+1].y,
                         bv0.x, bv0.y);
                mma_bf16(acc[m][0], av[2*m].z, av[2*m+1].z, av[2*m].w, av[2*m+1].w,
                         bu1.x, bu1.y);
                mma_bf16(acc[m][1], av[2*m].z, av[2*m+1].z, av[2*m].w, av[2*m+1].w,
                         bv1.x, bv1.y);
            }
        }

        // ---- write split-K partials: part[w][b][col] ----
        #pragma unroll
        for (int m = 0; m < 4; m++) {
            #pragma unroll
            for (int nf = 0; nf < 2; nf++) {
                int col = nf * 8 + 2 * tig;
                int b0r = m * 16 + gid;
                float2* p0 = (float2*)&part[((w * 64) + b0r) * 16 + col];
                float2* p1 = (float2*)&part[((w * 64) + b0r + 8) * 16 + col];
                *p0 = make_float2(acc[m][nf][0], acc[m][nf][1]);
                *p1 = make_float2(acc[m][nf][2], acc[m][nf][3]);
            }
        }
        __syncthreads();

        // ---- reduce + minimal c update (critical path to barrier arrive) ----
        float cn_s[2];
        #pragma unroll
        for (int rep = 0; rep < 2; rep++) {
            int rr = tid + rep * 256;
            int bb = rr >> 3, nn = rr & 7;
            float uu = 0.f, vv = 0.f;
            #pragma unroll
            for (int ww = 0; ww < 8; ww++) {
                uu += part[((ww * 64) + bb) * 16 + nn];
                vv += part[((ww * 64) + bb) * 16 + 8 + nn];
            }
            float iv = 1.0f / (1.0f + expf(-(t_xi[rep] + uu)));
            float fv = 1.0f / (1.0f + expf(-(t_xf[rep] + vv)));
            float cn = iv * t_xc[rep] + fv * t_c[rep];
            cn_s[rep] = cn;
            t_c[rep] = cn;                                       // register carry
            cbnext[cboff[rep]] = __float2bfloat16_rn(cn);
        }
        __syncthreads();

        const unsigned val = (unsigned)(epoch + step + 1);
        if (tid == 0)
            asm volatile("st.release.gpu.global.u32 [%0], %1;"
                         :: "l"(g_flags + bid), "r"(val) : "memory");

        // ---- barrier-wait shadow: h store + next-step operand prefetch ----
        #pragma unroll
        for (int rep = 0; rep < 2; rep++)
            h[offs[rep]] = tanhf(cn_s[rep]) + t_x[rep];

        if (step + 1 < LQ) {
            const int tn = reverse ? (LQ - 2 - step) : (step + 1);
            #pragma unroll
            for (int rep = 0; rep < 2; rep++) {
                size_t off = ((size_t)tn * BQ + bbs[rep]) * DQ + gns[rep];
                offs[rep] = off;
                t_xi[rep] = __ldcg(xi + off);
                t_xf[rep] = __ldcg(xf + off);
                t_xc[rep] = __ldcg(xc + off);
                t_x[rep]  = __ldcg(x + off);
            }
        }

        // ---- two-phase distributed flag barrier (wait part) ----
        if (bid == 0) {
            if (tid < NB_SCAN) {
                unsigned v;
                do {
                    asm volatile("ld.acquire.gpu.global.u32 %0, [%1];"
                                 : "=r"(v) : "l"(g_flags + tid) : "memory");
                } while (v < val);
            }
            __syncthreads();
            if (tid == 0)
                asm volatile("st.release.gpu.global.u32 [%0], %1;"
                             :: "l"(g_flags + NB_SCAN), "r"(val) : "memory");
        } else {
            if (tid == 0) {
                unsigned v;
                do {
                    asm volatile("ld.acquire.gpu.global.u32 %0, [%1];"
                                 : "=r"(v) : "l"(g_flags + NB_SCAN) : "memory");
                } while (v < val);
            }
        }
        __syncthreads();
    }

    // ---- final c handoff for the next scan ----
    #pragma unroll
    for (int rep = 0; rep < 2; rep++)
        chand[cboff[rep]] = t_c[rep];
}

// ---------------- launcher ----------------
extern "C" void kernel_launch(void* const* d_in, const int* in_sizes, int n_in,
                              void* d_out, int out_size)
{
    (void)in_sizes; (void)n_in; (void)out_size;

    cudaFuncSetAttribute(scan_kernel, cudaFuncAttributeMaxDynamicSharedMemorySize,
                         SCAN_SMEM_BYTES);
    cudaFuncSetAttribute(sgemm_bf16x2, cudaFuncAttributeMaxDynamicSharedMemorySize,
                         GEMM_SMEM_BYTES);

    const int*   xs  = (const int*)d_in[0];
    const float* emb = (const float*)d_in[1];
    const float* P[16];
    for (int i = 0; i < 16; i++) P[i] = (const float*)d_in[2 + i];
    // P: 0=fw_Wix 1=fw_Wic 2=fw_Wfx 3=fw_Wfc 4=fw_Wcx 5=fw_bi 6=fw_bf 7=fw_bc
    //    8=bw_Wix 9=bw_Wic 10=bw_Wfx 11=bw_Wfc 12=bw_Wcx 13=bw_bi 14=bw_bf 15=bw_bc

    float *px, *ph, *pxi, *pxf, *pxc, *pch;
    __nv_bfloat16 *pcbf, *pabh, *pabl, *pwth, *pwtl;
    unsigned* pflags;
    cudaGetSymbolAddress((void**)&px,    g_x);
    cudaGetSymbolAddress((void**)&ph,    g_h);
    cudaGetSymbolAddress((void**)&pxi,   g_xi);
    cudaGetSymbolAddress((void**)&pxf,   g_xf);
    cudaGetSymbolAddress((void**)&pxc,   g_xc);
    cudaGetSymbolAddress((void**)&pch,   g_chand);
    cudaGetSymbolAddress((void**)&pcbf,  g_cbf);
    cudaGetSymbolAddress((void**)&pabh,  g_abh);
    cudaGetSymbolAddress((void**)&pabl,  g_abl);
    cudaGetSymbolAddress((void**)&pwth,  g_wth);
    cudaGetSymbolAddress((void**)&pwtl,  g_wtl);
    cudaGetSymbolAddress((void**)&pflags, g_flags);
    float* out = (float*)d_out;

    embed_kernel<<<MQ * DQ / 4 / 256, 256>>>(xs, emb, px);
    zero_kernel<<<(BQ * DQ + 255) / 256, 256>>>(pch, BQ * DQ);
    zero_kernel<<<(BQ * DQ + 255) / 256, 256>>>((float*)pcbf, BQ * DQ); // 2*BQ*DQ bf16
    zero_kernel<<<1, 256>>>((float*)pflags, NB_SCAN + 1);

    // pre-split + transpose the 6 input-projection weight matrices (once)
    const int widx[6] = {0, 2, 4, 8, 10, 12};   // Wix, Wfx, Wcx for fw then bw
    dim3 tgrid(DQ / 32, DQ / 32), tblk(32, 8);
    for (int j = 0; j < 6; j++) {
        wsplit_t_kernel<<<tgrid, tblk>>>(P[widx[j]],
                                         pwth + (size_t)j * DQ * DQ,
                                         pwtl + (size_t)j * DQ * DQ);
    }

    const int AN4 = MQ * DQ / 4;                // 4M
    dim3 ggrid(DQ / TBN, MQ / TBM);             // (8, 128)
    for (int layer = 0; layer < 2; layer++) {
        // forward direction
        asplit_kernel<<<AN4 / 256, 256>>>((const float4*)px, (uint2*)pabh, (uint2*)pabl, AN4);
        sgemm_bf16x2<<<ggrid, 256, GEMM_SMEM_BYTES>>>(pabh, pabl,
            pwth + 0 * (size_t)DQ * DQ, pwtl + 0 * (size_t)DQ * DQ, P[5], pxi);
        sgemm_bf16x2<<<ggrid, 256, GEMM_SMEM_BYTES>>>(pabh, pabl,
            pwth + 1 * (size_t)DQ * DQ, pwtl + 1 * (size_t)DQ * DQ, P[6], pxf);
        sgemm_bf16x2<<<ggrid, 256, GEMM_SMEM_BYTES>>>(pabh, pabl,
            pwth + 2 * (size_t)DQ * DQ, pwtl + 2 * (size_t)DQ * DQ, P[7], pxc);
        scan_kernel<<<NB_SCAN, 256, SCAN_SMEM_BYTES>>>(px, pxi, pxf, pxc,
            P[1], P[3], pch, pcbf, ph, 0, (layer * 2 + 0) * LQ);
        // backward direction
        asplit_kernel<<<AN4 / 256, 256>>>((const float4*)ph, (uint2*)pabh, (uint2*)pabl, AN4);
        sgemm_bf16x2<<<ggrid, 256, GEMM_SMEM_BYTES>>>(pabh, pabl,
            pwth + 3 * (size_t)DQ * DQ, pwtl + 3 * (size_t)DQ * DQ, P[13], pxi);
        sgemm_bf16x2<<<ggrid, 256, GEMM_SMEM_BYTES>>>(pabh, pabl,
            pwth + 4 * (size_t)DQ * DQ, pwtl + 4 * (size_t)DQ * DQ, P[14], pxf);
        sgemm_bf16x2<<<ggrid, 256, GEMM_SMEM_BYTES>>>(pabh, pabl,
            pwth + 5 * (size_t)DQ * DQ, pwtl + 5 * (size_t)DQ * DQ, P[15], pxc);
        float* ho = (layer == 1) ? out : px;
        scan_kernel<<<NB_SCAN, 256, SCAN_SMEM_BYTES>>>(ph, pxi, pxf, pxc,
            P[9], P[11], pch, pcbf, ho, 1, (layer * 2 + 1) * LQ);
    }
}

// round 15
// speedup vs baseline: 1.0395x; 1.0395x over previous
#include <cuda_runtime.h>
#include <cuda_bf16.h>
#include <math.h>
#include <stdint.h>

#define LQ 256
#define BQ 64
#define DQ 1024
#define VQ 32000
#define MQ (LQ * BQ)          // 16384 rows for projections
#define NB_SCAN 128

// ---------------- scratch (static device globals; no allocation) ----------------
__device__ float g_x [LQ * BQ * DQ];   // current layer input / bw output
__device__ float g_h [LQ * BQ * DQ];   // fw output ("first")
__device__ float g_xi[LQ * BQ * DQ];
__device__ float g_xf[LQ * BQ * DQ];
__device__ float g_xc[LQ * BQ * DQ];
__device__ float g_chand[BQ * DQ];               // fp32 c handoff between scans
__device__ __nv_bfloat16 g_cbf[2 * BQ * DQ];     // bf16 shadow of c for mma loads
__device__ __nv_bfloat16 g_abh[LQ * BQ * DQ];    // GEMM A operand bf16 hi
__device__ __nv_bfloat16 g_abl[LQ * BQ * DQ];    // GEMM A operand bf16 lo
__device__ __nv_bfloat16 g_wth[6 * DQ * DQ];     // weights transposed [N][K] bf16 hi
__device__ __nv_bfloat16 g_wtl[6 * DQ * DQ];     // weights transposed [N][K] bf16 lo
__device__ unsigned g_flags[NB_SCAN + 1];        // per-CTA arrival flags + go word

// ---------------- embedding gather ----------------
__global__ __launch_bounds__(256) void embed_kernel(
    const int* __restrict__ xs, const float* __restrict__ emb, float* __restrict__ x)
{
    int i = blockIdx.x * 256 + threadIdx.x;     // over MQ*DQ/4 float4's
    int tokpos = i >> 8;                        // DQ/4 = 256 float4 per row
    int d4 = i & 255;
    int tok = xs[tokpos];
    tok = min(max(tok, 0), VQ - 1);
    ((float4*)x)[i] = ((const float4*)(emb + (size_t)tok * DQ))[d4];
}

__global__ __launch_bounds__(256) void zero_kernel(float* __restrict__ p, int n)
{
    int i = blockIdx.x * 256 + threadIdx.x;
    if (i < n) p[i] = 0.0f;
}

// ---------------- mma helpers ----------------
__device__ __forceinline__ void mma_bf16(float d[4],
    uint32_t a0, uint32_t a1, uint32_t a2, uint32_t a3,
    uint32_t b0, uint32_t b1)
{
    asm volatile(
        "mma.sync.aligned.m16n8k16.row.col.f32.bf16.bf16.f32 "
        "{%0,%1,%2,%3}, {%4,%5,%6,%7}, {%8,%9}, {%0,%1,%2,%3};"
        : "+f"(d[0]), "+f"(d[1]), "+f"(d[2]), "+f"(d[3])
        : "r"(a0), "r"(a1), "r"(a2), "r"(a3), "r"(b0), "r"(b1));
}

__device__ __forceinline__ uint32_t pack_bf16x2(float lo, float hi)
{
    __nv_bfloat162 p = __floats2bfloat162_rn(lo, hi);
    return *reinterpret_cast<uint32_t*>(&p);
}

__device__ __forceinline__ void split_bf16(float v, __nv_bfloat16& h, __nv_bfloat16& l)
{
    h = __float2bfloat16_rn(v);
    l = __float2bfloat16_rn(v - __bfloat162float(h));
}

// ---------------- A split kernel: fp32 -> bf16 hi/lo (row-major) --------------
__global__ __launch_bounds__(256) void asplit_kernel(
    const float4* __restrict__ src, uint2* __restrict__ hi, uint2* __restrict__ lo, int n4)
{
    int i = blockIdx.x * 256 + threadIdx.x;
    if (i >= n4) return;
    float4 v = src[i];
    __nv_bfloat16 hx, lx, hy, ly, hz, lz, hw, lw;
    split_bf16(v.x, hx, lx);
    split_bf16(v.y, hy, ly);
    split_bf16(v.z, hz, lz);
    split_bf16(v.w, hw, lw);
    uint2 hv, lv;
    hv.x = pack_bf16x2(__bfloat162float(hx), __bfloat162float(hy));
    hv.y = pack_bf16x2(__bfloat162float(hz), __bfloat162float(hw));
    lv.x = pack_bf16x2(__bfloat162float(lx), __bfloat162float(ly));
    lv.y = pack_bf16x2(__bfloat162float(lz), __bfloat162float(lw));
    hi[i] = hv;
    lo[i] = lv;
}

// ---------------- W transpose+split kernel: W[K][N] fp32 -> Wt[N][K] bf16 hi/lo
__global__ void wsplit_t_kernel(const float* __restrict__ W,
                                __nv_bfloat16* __restrict__ Th,
                                __nv_bfloat16* __restrict__ Tl)
{
    __shared__ float tile[32][33];
    int tx = threadIdx.x, ty = threadIdx.y;     // 32 x 8
    int n0 = blockIdx.x * 32, k0 = blockIdx.y * 32;
    #pragma unroll
    for (int i = 0; i < 32; i += 8)
        tile[ty + i][tx] = W[(size_t)(k0 + ty + i) * DQ + n0 + tx];
    __syncthreads();
    #pragma unroll
    for (int i = 0; i < 32; i += 8) {
        float v = tile[tx][ty + i];             // = W[k0+tx][n0+ty+i]
        __nv_bfloat16 h, l;
        split_bf16(v, h, l);
        size_t o = (size_t)(n0 + ty + i) * DQ + k0 + tx;
        Th[o] = h;
        Tl[o] = l;
    }
}

// ---------------- 2xBF16 tensor-core GEMM + bias: C = A@W + bias --------------
// __launch_bounds__(256, 2): cap regs at 128 so TWO CTAs co-reside per SM,
// overlapping one CTA's syncthreads/load bubbles with the other's HMMAs.
#define TBM 128
#define TBN 128
#define TBK 16
#define BFPAD 8                        // bf16 pad -> stride 24 (conflict-free)
#define BF_STRIDE (TBK + BFPAD)        // 24 bf16
#define BF_TILE (128 * BF_STRIDE)      // 3072 bf16 per buf (A and B same shape)
#define OFF_ABH 0
#define OFF_ABL (2 * BF_TILE)
#define OFF_BBH (4 * BF_TILE)
#define OFF_BBL (6 * BF_TILE)
#define GEMM_SMEM_BYTES (8 * BF_TILE * 2)   // 49152

__global__ __launch_bounds__(256, 2) void sgemm_bf16x2(
    const __nv_bfloat16* __restrict__ Ahi, const __nv_bfloat16* __restrict__ Alo,
    const __nv_bfloat16* __restrict__ Wth, const __nv_bfloat16* __restrict__ Wtl,
    const float* __restrict__ bias, float* __restrict__ C)
{
    extern __shared__ __align__(16) __nv_bfloat16 smb[];

    const int tid  = threadIdx.x;
    const int lane = tid & 31;
    const int w    = tid >> 5;
    const int gid  = lane >> 2;
    const int tig  = lane & 3;
    const int wm0  = (w >> 2) * 64;   // warp m offset in tile
    const int wn0  = (w & 3) * 32;    // warp n offset in tile
    const int m0   = blockIdx.y * TBM;
    const int n0   = blockIdx.x * TBN;

    float acc[4][4][4];
    #pragma unroll
    for (int mf = 0; mf < 4; mf++)
        #pragma unroll
        for (int nf = 0; nf < 4; nf++)
            #pragma unroll
            for (int r = 0; r < 4; r++) acc[mf][nf][r] = 0.f;

    auto load_tiles = [&](int it, int buf) {
        int k0 = it * TBK;
        int row = tid >> 1, seg = tid & 1;
        {
            size_t goff = (size_t)(m0 + row) * DQ + k0 + seg * 8;
            int soff = buf * BF_TILE + row * BF_STRIDE + seg * 8;
            uint32_t d0 = (uint32_t)__cvta_generic_to_shared(&smb[OFF_ABH + soff]);
            uint32_t d1 = (uint32_t)__cvta_generic_to_shared(&smb[OFF_ABL + soff]);
            asm volatile("cp.async.ca.shared.global [%0], [%1], 16;" :: "r"(d0), "l"(Ahi + goff));
            asm volatile("cp.async.ca.shared.global [%0], [%1], 16;" :: "r"(d1), "l"(Alo + goff));
        }
        {
            size_t goff = (size_t)(n0 + row) * DQ + k0 + seg * 8;
            int soff = buf * BF_TILE + row * BF_STRIDE + seg * 8;
            uint32_t d0 = (uint32_t)__cvta_generic_to_shared(&smb[OFF_BBH + soff]);
            uint32_t d1 = (uint32_t)__cvta_generic_to_shared(&smb[OFF_BBL + soff]);
            asm volatile("cp.async.ca.shared.global [%0], [%1], 16;" :: "r"(d0), "l"(Wth + goff));
            asm volatile("cp.async.ca.shared.global [%0], [%1], 16;" :: "r"(d1), "l"(Wtl + goff));
        }
        asm volatile("cp.async.commit_group;");
    };

    load_tiles(0, 0);

    const int NIT = DQ / TBK;   // 64
    for (int it = 0; it < NIT; it++) {
        int buf = it & 1;
        if (it + 1 < NIT) {
            load_tiles(it + 1, buf ^ 1);
            asm volatile("cp.async.wait_group 1;");
        } else {
            asm volatile("cp.async.wait_group 0;");
        }
        __syncthreads();

        uint32_t ah[4][4], al[4][4];
        #pragma unroll
        for (int mf = 0; mf < 4; mf++) {
            int r = wm0 + mf * 16;
            int i0 = buf * BF_TILE + (r + gid) * BF_STRIDE + 2 * tig;
            int i1 = buf * BF_TILE + (r + gid + 8) * BF_STRIDE + 2 * tig;
            ah[mf][0] = *(const uint32_t*)&smb[OFF_ABH + i0];
            ah[mf][1] = *(const uint32_t*)&smb[OFF_ABH + i1];
            ah[mf][2] = *(const uint32_t*)&smb[OFF_ABH + i0 + 8];
            ah[mf][3] = *(const uint32_t*)&smb[OFF_ABH + i1 + 8];
            al[mf][0] = *(const uint32_t*)&smb[OFF_ABL + i0];
            al[mf][1] = *(const uint32_t*)&smb[OFF_ABL + i1];
            al[mf][2] = *(const uint32_t*)&smb[OFF_ABL + i0 + 8];
            al[mf][3] = *(const uint32_t*)&smb[OFF_ABL + i1 + 8];
        }
        uint32_t bh[4][2], bl[4][2];
        #pragma unroll
        for (int nf = 0; nf < 4; nf++) {
            int cN = wn0 + nf * 8 + gid;
            int j0 = buf * BF_TILE + cN * BF_STRIDE + 2 * tig;
            bh[nf][0] = *(const uint32_t*)&smb[OFF_BBH + j0];
            bh[nf][1] = *(const uint32_t*)&smb[OFF_BBH + j0 + 8];
            bl[nf][0] = *(const uint32_t*)&smb[OFF_BBL + j0];
            bl[nf][1] = *(const uint32_t*)&smb[OFF_BBL + j0 + 8];
        }
        #pragma unroll
        for (int mf = 0; mf < 4; mf++)
            #pragma unroll
            for (int nf = 0; nf < 4; nf++) {
                mma_bf16(acc[mf][nf], ah[mf][0], ah[mf][1], ah[mf][2], ah[mf][3],
                         bh[nf][0], bh[nf][1]);
                mma_bf16(acc[mf][nf], al[mf][0], al[mf][1], al[mf][2], al[mf][3],
                         bh[nf][0], bh[nf][1]);
                mma_bf16(acc[mf][nf], ah[mf][0], ah[mf][1], ah[mf][2], ah[mf][3],
                         bl[nf][0], bl[nf][1]);
            }
        __syncthreads();
    }

    #pragma unroll
    for (int mf = 0; mf < 4; mf++) {
        #pragma unroll
        for (int nf = 0; nf < 4; nf++) {
            int r0 = m0 + wm0 + mf * 16 + gid;
            int cN = n0 + wn0 + nf * 8 + 2 * tig;
            float2 bv = *(const float2*)(bias + cN);
            float2 o0 = make_float2(acc[mf][nf][0] + bv.x, acc[mf][nf][1] + bv.y);
            float2 o1 = make_float2(acc[mf][nf][2] + bv.x, acc[mf][nf][3] + bv.y);
            *(float2*)(C + (size_t)r0 * DQ + cN) = o0;
            *(float2*)(C + (size_t)(r0 + 8) * DQ + cN) = o1;
        }
    }
}

// ---------------- persistent scan kernel (bf16 mma, register fp32 recurrence) --
// 128 CTAs x 256 threads; CTA owns 8 output columns. (R13 structure: prefetch
// at step top — hidden under mma phase; minimal chain to barrier arrive.)
// SMEM: Bs 64 mma * 2 nf * 32 lanes * 8B = 32 KB, partials 32 KB
#define SCAN_SMEM_BYTES (32768 + 32768)

__global__ __launch_bounds__(256) void scan_kernel(
    const float* __restrict__ x,  const float* __restrict__ xi,
    const float* __restrict__ xf, const float* __restrict__ xc,
    const float* __restrict__ Wic, const float* __restrict__ Wfc,
    float* __restrict__ chand,             // [BQ*DQ] fp32 handoff
    __nv_bfloat16* __restrict__ cbf,       // [2][BQ*DQ] bf16 shadow
    float* __restrict__ h, int reverse, int epoch)
{
    extern __shared__ __align__(16) char smem_raw[];
    uint2* Bs   = (uint2*)smem_raw;                  // [64 mma][2 nf][32 lanes]
    float* part = (float*)(smem_raw + 32768);        // [8 warps][64 b][16 cols]

    const int tid  = threadIdx.x;
    const int lane = tid & 31;
    const int w    = tid >> 5;
    const int gid  = lane >> 2;       // groupID 0..7
    const int tig  = lane & 3;        // threadID in group
    const int n0   = blockIdx.x * 8;  // this CTA's output column base
    const int bid  = blockIdx.x;

    // ---- pre-lay weights bf16 in fragment order (once per scan) ----
    for (int idx = tid; idx < 64 * 2 * 32; idx += 256) {
        int l    = idx & 31;
        int nf   = (idx >> 5) & 1;
        int mi   = idx >> 6;
        int s    = mi >> 1;
        int half = mi & 1;
        int k0   = 32 * s + 8 * (l & 3) + 4 * half;
        int col  = n0 + (l >> 2);
        const float* M = nf ? Wfc : Wic;
        uint2 v;
        v.x = pack_bf16x2(M[(size_t)(k0 + 0) * DQ + col], M[(size_t)(k0 + 1) * DQ + col]);
        v.y = pack_bf16x2(M[(size_t)(k0 + 2) * DQ + col], M[(size_t)(k0 + 3) * DQ + col]);
        Bs[idx] = v;
    }
    __syncthreads();

    // tail addressing: 2 reps x 256 threads cover 64 b x 8 n cell updates;
    // fp32 c carried in registers across all steps.
    int bbs[2], gns[2];
    float t_c[2];
    #pragma unroll
    for (int rep = 0; rep < 2; rep++) {
        int rr = tid + rep * 256;
        bbs[rep] = rr >> 3;
        gns[rep] = n0 + (rr & 7);
        t_c[rep] = chand[(size_t)bbs[rep] * DQ + gns[rep]];   // initial c
    }

    for (int step = 0; step < LQ; step++) {
        const int t = reverse ? (LQ - 1 - step) : step;
        const __nv_bfloat16* cbprev = cbf + (step & 1) * (BQ * DQ);
        __nv_bfloat16* cbnext = cbf + ((step + 1) & 1) * (BQ * DQ);

        // ---- prefetch tail operands early (hidden under mma phase) ----
        float t_xi[2], t_xf[2], t_xc[2], t_x[2];
        size_t offs[2];
        #pragma unroll
        for (int rep = 0; rep < 2; rep++) {
            size_t off = ((size_t)t * BQ + bbs[rep]) * DQ + gns[rep];
            offs[rep] = off;
            t_xi[rep] = __ldcg(xi + off);
            t_xf[rep] = __ldcg(xf + off);
            t_xc[rep] = __ldcg(xc + off);
            t_x[rep]  = __ldcg(x + off);
        }

        float acc[4][2][4];
        #pragma unroll
        for (int m = 0; m < 4; m++)
            #pragma unroll
            for (int nf = 0; nf < 2; nf++)
                #pragma unroll
                for (int r = 0; r < 4; r++) acc[m][nf][r] = 0.f;

        #pragma unroll
        for (int j = 0; j < 4; j++) {
            int s = 4 * w + j;
            uint2 bu0 = Bs[((2 * s + 0) * 2 + 0) * 32 + lane];
            uint2 bv0 = Bs[((2 * s + 0) * 2 + 1) * 32 + lane];
            uint2 bu1 = Bs[((2 * s + 1) * 2 + 0) * 32 + lane];
            uint2 bv1 = Bs[((2 * s + 1) * 2 + 1) * 32 + lane];
            const __nv_bfloat16* abase = cbprev + (size_t)gid * DQ + 32 * s + 8 * tig;
            uint4 av[8];
            #pragma unroll
            for (int m = 0; m < 4; m++) {
                av[2 * m]     = __ldcg((const uint4*)(abase + (size_t)(m * 16) * DQ));
                av[2 * m + 1] = __ldcg((const uint4*)(abase + (size_t)(m * 16 + 8) * DQ));
            }
            #pragma unroll
            for (int m = 0; m < 4; m++) {
                mma_bf16(acc[m][0], av[2*m].x, av[2*m+1].x, av[2*m].y, av[2*m+1].y,
                         bu0.x, bu0.y);
                mma_bf16(acc[m][1], av[2*m].x, av[2*m+1].x, av[2*m].y, av[2*m+1].y,
                         bv0.x, bv0.y);
                mma_bf16(acc[m][0], av[2*m].z, av[2*m+1].z, av[2*m].w, av[2*m+1].w,
                         bu1.x, bu1.y);
                mma_bf16(acc[m][1], av[2*m].z, av[2*m+1].z, av[2*m].w, av[2*m+1].w,
                         bv1.x, bv1.y);
            }
        }

        // ---- write split-K partials: part[w][b][col] ----
        #pragma unroll
        for (int m = 0; m < 4; m++) {
            #pragma unroll
            for (int nf = 0; nf < 2; nf++) {
                int col = nf * 8 + 2 * tig;
                int b0r = m * 16 + gid;
                float2* p0 = (float2*)&part[((w * 64) + b0r) * 16 + col];
                float2* p1 = (float2*)&part[((w * 64) + b0r + 8) * 16 + col];
                *p0 = make_float2(acc[m][nf][0], acc[m][nf][1]);
                *p1 = make_float2(acc[m][nf][2], acc[m][nf][3]);
            }
        }
        __syncthreads();

        // ---- reduce over warps + elementwise update: 64b x 8n, 2 per thread ----
        #pragma unroll
        for (int rep = 0; rep < 2; rep++) {
            int rr = tid + rep * 256;
            int bb = rr >> 3, nn = rr & 7;
            float uu = 0.f, vv = 0.f;
            #pragma unroll
            for (int ww = 0; ww < 8; ww++) {
                uu += part[((ww * 64) + bb) * 16 + nn];
                vv += part[((ww * 64) + bb) * 16 + 8 + nn];
            }
            float iv = 1.0f / (1.0f + expf(-(t_xi[rep] + uu)));
            float fv = 1.0f / (1.0f + expf(-(t_xf[rep] + vv)));
            float cn = iv * t_xc[rep] + fv * t_c[rep];
            t_c[rep] = cn;                                       // register carry
            cbnext[(size_t)bb * DQ + gns[rep]] = __float2bfloat16_rn(cn);
            h[offs[rep]] = tanhf(cn) + t_x[rep];
        }

        // ---- two-phase distributed flag barrier ----
        {
            const unsigned val = (unsigned)(epoch + step + 1);
            __syncthreads();
            if (tid == 0)
                asm volatile("st.release.gpu.global.u32 [%0], %1;"
                             :: "l"(g_flags + bid), "r"(val) : "memory");
            if (bid == 0) {
                if (tid < NB_SCAN) {
                    unsigned v;
                    do {
                        asm volatile("ld.acquire.gpu.global.u32 %0, [%1];"
                                     : "=r"(v) : "l"(g_flags + tid) : "memory");
                    } while (v < val);
                }
                __syncthreads();
                if (tid == 0)
                    asm volatile("st.release.gpu.global.u32 [%0], %1;"
                                 :: "l"(g_flags + NB_SCAN), "r"(val) : "memory");
            } else {
                if (tid == 0) {
                    unsigned v;
                    do {
                        asm volatile("ld.acquire.gpu.global.u32 %0, [%1];"
                                     : "=r"(v) : "l"(g_flags + NB_SCAN) : "memory");
                    } while (v < val);
                }
            }
            __syncthreads();
        }
    }

    // ---- final c handoff for the next scan ----
    #pragma unroll
    for (int rep = 0; rep < 2; rep++)
        chand[(size_t)bbs[rep] * DQ + gns[rep]] = t_c[rep];
}

// ---------------- launcher ----------------
extern "C" void kernel_launch(void* const* d_in, const int* in_sizes, int n_in,
                              void* d_out, int out_size)
{
    (void)in_sizes; (void)n_in; (void)out_size;

    cudaFuncSetAttribute(scan_kernel, cudaFuncAttributeMaxDynamicSharedMemorySize,
                         SCAN_SMEM_BYTES);
    cudaFuncSetAttribute(sgemm_bf16x2, cudaFuncAttributeMaxDynamicSharedMemorySize,
                         GEMM_SMEM_BYTES);

    const int*   xs  = (const int*)d_in[0];
    const float* emb = (const float*)d_in[1];
    const float* P[16];
    for (int i = 0; i < 16; i++) P[i] = (const float*)d_in[2 + i];
    // P: 0=fw_Wix 1=fw_Wic 2=fw_Wfx 3=fw_Wfc 4=fw_Wcx 5=fw_bi 6=fw_bf 7=fw_bc
    //    8=bw_Wix 9=bw_Wic 10=bw_Wfx 11=bw_Wfc 12=bw_Wcx 13=bw_bi 14=bw_bf 15=bw_bc

    float *px, *ph, *pxi, *pxf, *pxc, *pch;
    __nv_bfloat16 *pcbf, *pabh, *pabl, *pwth, *pwtl;
    unsigned* pflags;
    cudaGetSymbolAddress((void**)&px,    g_x);
    cudaGetSymbolAddress((void**)&ph,    g_h);
    cudaGetSymbolAddress((void**)&pxi,   g_xi);
    cudaGetSymbolAddress((void**)&pxf,   g_xf);
    cudaGetSymbolAddress((void**)&pxc,   g_xc);
    cudaGetSymbolAddress((void**)&pch,   g_chand);
    cudaGetSymbolAddress((void**)&pcbf,  g_cbf);
    cudaGetSymbolAddress((void**)&pabh,  g_abh);
    cudaGetSymbolAddress((void**)&pabl,  g_abl);
    cudaGetSymbolAddress((void**)&pwth,  g_wth);
    cudaGetSymbolAddress((void**)&pwtl,  g_wtl);
    cudaGetSymbolAddress((void**)&pflags, g_flags);
    float* out = (float*)d_out;

    embed_kernel<<<MQ * DQ / 4 / 256, 256>>>(xs, emb, px);
    zero_kernel<<<(BQ * DQ + 255) / 256, 256>>>(pch, BQ * DQ);
    zero_kernel<<<(BQ * DQ + 255) / 256, 256>>>((float*)pcbf, BQ * DQ); // 2*BQ*DQ bf16
    zero_kernel<<<1, 256>>>((float*)pflags, NB_SCAN + 1);

    // pre-split + transpose the 6 input-projection weight matrices (once)
    const int widx[6] = {0, 2, 4, 8, 10, 12};   // Wix, Wfx, Wcx for fw then bw
    dim3 tgrid(DQ / 32, DQ / 32), tblk(32, 8);
    for (int j = 0; j < 6; j++) {
        wsplit_t_kernel<<<tgrid, tblk>>>(P[widx[j]],
                                         pwth + (size_t)j * DQ * DQ,
                                         pwtl + (size_t)j * DQ * DQ);
    }

    const int AN4 = MQ * DQ / 4;                // 4M
    dim3 ggrid(DQ / TBN, MQ / TBM);             // (8, 128)
    for (int layer = 0; layer < 2; layer++) {
        // forward direction
        asplit_kernel<<<AN4 / 256, 256>>>((const float4*)px, (uint2*)pabh, (uint2*)pabl, AN4);
        sgemm_bf16x2<<<ggrid, 256, GEMM_SMEM_BYTES>>>(pabh, pabl,
            pwth + 0 * (size_t)DQ * DQ, pwtl + 0 * (size_t)DQ * DQ, P[5], pxi);
        sgemm_bf16x2<<<ggrid, 256, GEMM_SMEM_BYTES>>>(pabh, pabl,
            pwth + 1 * (size_t)DQ * DQ, pwtl + 1 * (size_t)DQ * DQ, P[6], pxf);
        sgemm_bf16x2<<<ggrid, 256, GEMM_SMEM_BYTES>>>(pabh, pabl,
            pwth + 2 * (size_t)DQ * DQ, pwtl + 2 * (size_t)DQ * DQ, P[7], pxc);
        scan_kernel<<<NB_SCAN, 256, SCAN_SMEM_BYTES>>>(px, pxi, pxf, pxc,
            P[1], P[3], pch, pcbf, ph, 0, (layer * 2 + 0) * LQ);
        // backward direction
        asplit_kernel<<<AN4 / 256, 256>>>((const float4*)ph, (uint2*)pabh, (uint2*)pabl, AN4);
        sgemm_bf16x2<<<ggrid, 256, GEMM_SMEM_BYTES>>>(pabh, pabl,
            pwth + 3 * (size_t)DQ * DQ, pwtl + 3 * (size_t)DQ * DQ, P[13], pxi);
        sgemm_bf16x2<<<ggrid, 256, GEMM_SMEM_BYTES>>>(pabh, pabl,
            pwth + 4 * (size_t)DQ * DQ, pwtl + 4 * (size_t)DQ * DQ, P[14], pxf);
        sgemm_bf16x2<<<ggrid, 256, GEMM_SMEM_BYTES>>>(pabh, pabl,
            pwth + 5 * (size_t)DQ * DQ, pwtl + 5 * (size_t)DQ * DQ, P[15], pxc);
        float* ho = (layer == 1) ? out : px;
        scan_kernel<<<NB_SCAN, 256, SCAN_SMEM_BYTES>>>(ph, pxi, pxf, pxc,
            P[9], P[11], pch, pcbf, ho, 1, (layer * 2 + 1) * LQ);
    }
}

// round 16
// speedup vs baseline: 1.0937x; 1.0521x over previous
#include <cuda_runtime.h>
#include <cuda_bf16.h>
#include <math.h>
#include <stdint.h>

#define LQ 256
#define BQ 64
#define DQ 1024
#define VQ 32000
#define MQ (LQ * BQ)          // 16384 rows for projections
#define NB_SCAN 128

// ---------------- scratch (static device globals; no allocation) ----------------
__device__ float g_x [LQ * BQ * DQ];   // current layer input / bw output
__device__ float g_h [LQ * BQ * DQ];   // fw output ("first")
__device__ float g_xi[LQ * BQ * DQ];
__device__ float g_xf[LQ * BQ * DQ];
__device__ float g_xc[LQ * BQ * DQ];
__device__ float g_chand[BQ * DQ];               // fp32 c handoff between scans
__device__ __nv_bfloat16 g_cbf[2 * BQ * DQ];     // bf16 shadow of c for mma loads
__device__ __nv_bfloat16 g_abh[LQ * BQ * DQ];    // GEMM A operand bf16 hi
__device__ __nv_bfloat16 g_abl[LQ * BQ * DQ];    // GEMM A operand bf16 lo
__device__ __nv_bfloat16 g_wth[6 * DQ * DQ];     // weights transposed [N][K] bf16 hi
__device__ __nv_bfloat16 g_wtl[6 * DQ * DQ];     // weights transposed [N][K] bf16 lo
__device__ unsigned g_flags[NB_SCAN];            // per-CTA step flags (monotonic)

// ---------------- embedding gather ----------------
__global__ __launch_bounds__(256) void embed_kernel(
    const int* __restrict__ xs, const float* __restrict__ emb, float* __restrict__ x)
{
    int i = blockIdx.x * 256 + threadIdx.x;     // over MQ*DQ/4 float4's
    int tokpos = i >> 8;                        // DQ/4 = 256 float4 per row
    int d4 = i & 255;
    int tok = xs[tokpos];
    tok = min(max(tok, 0), VQ - 1);
    ((float4*)x)[i] = ((const float4*)(emb + (size_t)tok * DQ))[d4];
}

__global__ __launch_bounds__(256) void zero_kernel(float* __restrict__ p, int n)
{
    int i = blockIdx.x * 256 + threadIdx.x;
    if (i < n) p[i] = 0.0f;
}

// ---------------- mma helpers ----------------
__device__ __forceinline__ void mma_bf16(float d[4],
    uint32_t a0, uint32_t a1, uint32_t a2, uint32_t a3,
    uint32_t b0, uint32_t b1)
{
    asm volatile(
        "mma.sync.aligned.m16n8k16.row.col.f32.bf16.bf16.f32 "
        "{%0,%1,%2,%3}, {%4,%5,%6,%7}, {%8,%9}, {%0,%1,%2,%3};"
        : "+f"(d[0]), "+f"(d[1]), "+f"(d[2]), "+f"(d[3])
        : "r"(a0), "r"(a1), "r"(a2), "r"(a3), "r"(b0), "r"(b1));
}

__device__ __forceinline__ uint32_t pack_bf16x2(float lo, float hi)
{
    __nv_bfloat162 p = __floats2bfloat162_rn(lo, hi);
    return *reinterpret_cast<uint32_t*>(&p);
}

__device__ __forceinline__ void split_bf16(float v, __nv_bfloat16& h, __nv_bfloat16& l)
{
    h = __float2bfloat16_rn(v);
    l = __float2bfloat16_rn(v - __bfloat162float(h));
}

// ---------------- A split kernel: fp32 -> bf16 hi/lo (row-major) --------------
__global__ __launch_bounds__(256) void asplit_kernel(
    const float4* __restrict__ src, uint2* __restrict__ hi, uint2* __restrict__ lo, int n4)
{
    int i = blockIdx.x * 256 + threadIdx.x;
    if (i >= n4) return;
    float4 v = src[i];
    __nv_bfloat16 hx, lx, hy, ly, hz, lz, hw, lw;
    split_bf16(v.x, hx, lx);
    split_bf16(v.y, hy, ly);
    split_bf16(v.z, hz, lz);
    split_bf16(v.w, hw, lw);
    uint2 hv, lv;
    hv.x = pack_bf16x2(__bfloat162float(hx), __bfloat162float(hy));
    hv.y = pack_bf16x2(__bfloat162float(hz), __bfloat162float(hw));
    lv.x = pack_bf16x2(__bfloat162float(lx), __bfloat162float(ly));
    lv.y = pack_bf16x2(__bfloat162float(lz), __bfloat162float(lw));
    hi[i] = hv;
    lo[i] = lv;
}

// ---------------- W transpose+split kernel: W[K][N] fp32 -> Wt[N][K] bf16 hi/lo
__global__ void wsplit_t_kernel(const float* __restrict__ W,
                                __nv_bfloat16* __restrict__ Th,
                                __nv_bfloat16* __restrict__ Tl)
{
    __shared__ float tile[32][33];
    int tx = threadIdx.x, ty = threadIdx.y;     // 32 x 8
    int n0 = blockIdx.x * 32, k0 = blockIdx.y * 32;
    #pragma unroll
    for (int i = 0; i < 32; i += 8)
        tile[ty + i][tx] = W[(size_t)(k0 + ty + i) * DQ + n0 + tx];
    __syncthreads();
    #pragma unroll
    for (int i = 0; i < 32; i += 8) {
        float v = tile[tx][ty + i];             // = W[k0+tx][n0+ty+i]
        __nv_bfloat16 h, l;
        split_bf16(v, h, l);
        size_t o = (size_t)(n0 + ty + i) * DQ + k0 + tx;
        Th[o] = h;
        Tl[o] = l;
    }
}

// ---------------- 2xBF16 tensor-core GEMM + bias: C = A@W + bias --------------
#define TBM 128
#define TBN 128
#define TBK 16
#define BFPAD 8                        // bf16 pad -> stride 24 (conflict-free)
#define BF_STRIDE (TBK + BFPAD)        // 24 bf16
#define BF_TILE (128 * BF_STRIDE)      // 3072 bf16 per buf (A and B same shape)
#define OFF_ABH 0
#define OFF_ABL (2 * BF_TILE)
#define OFF_BBH (4 * BF_TILE)
#define OFF_BBL (6 * BF_TILE)
#define GEMM_SMEM_BYTES (8 * BF_TILE * 2)   // 49152

__global__ __launch_bounds__(256) void sgemm_bf16x2(
    const __nv_bfloat16* __restrict__ Ahi, const __nv_bfloat16* __restrict__ Alo,
    const __nv_bfloat16* __restrict__ Wth, const __nv_bfloat16* __restrict__ Wtl,
    const float* __restrict__ bias, float* __restrict__ C)
{
    extern __shared__ __align__(16) __nv_bfloat16 smb[];

    const int tid  = threadIdx.x;
    const int lane = tid & 31;
    const int w    = tid >> 5;
    const int gid  = lane >> 2;
    const int tig  = lane & 3;
    const int wm0  = (w >> 2) * 64;   // warp m offset in tile
    const int wn0  = (w & 3) * 32;    // warp n offset in tile
    const int m0   = blockIdx.y * TBM;
    const int n0   = blockIdx.x * TBN;

    float acc[4][4][4];
    #pragma unroll
    for (int mf = 0; mf < 4; mf++)
        #pragma unroll
        for (int nf = 0; nf < 4; nf++)
            #pragma unroll
            for (int r = 0; r < 4; r++) acc[mf][nf][r] = 0.f;

    auto load_tiles = [&](int it, int buf) {
        int k0 = it * TBK;
        int row = tid >> 1, seg = tid & 1;
        {
            size_t goff = (size_t)(m0 + row) * DQ + k0 + seg * 8;
            int soff = buf * BF_TILE + row * BF_STRIDE + seg * 8;
            uint32_t d0 = (uint32_t)__cvta_generic_to_shared(&smb[OFF_ABH + soff]);
            uint32_t d1 = (uint32_t)__cvta_generic_to_shared(&smb[OFF_ABL + soff]);
            asm volatile("cp.async.ca.shared.global [%0], [%1], 16;" :: "r"(d0), "l"(Ahi + goff));
            asm volatile("cp.async.ca.shared.global [%0], [%1], 16;" :: "r"(d1), "l"(Alo + goff));
        }
        {
            size_t goff = (size_t)(n0 + row) * DQ + k0 + seg * 8;
            int soff = buf * BF_TILE + row * BF_STRIDE + seg * 8;
            uint32_t d0 = (uint32_t)__cvta_generic_to_shared(&smb[OFF_BBH + soff]);
            uint32_t d1 = (uint32_t)__cvta_generic_to_shared(&smb[OFF_BBL + soff]);
            asm volatile("cp.async.ca.shared.global [%0], [%1], 16;" :: "r"(d0), "l"(Wth + goff));
            asm volatile("cp.async.ca.shared.global [%0], [%1], 16;" :: "r"(d1), "l"(Wtl + goff));
        }
        asm volatile("cp.async.commit_group;");
    };

    load_tiles(0, 0);

    const int NIT = DQ / TBK;   // 64
    for (int it = 0; it < NIT; it++) {
        int buf = it & 1;
        if (it + 1 < NIT) {
            load_tiles(it + 1, buf ^ 1);
            asm volatile("cp.async.wait_group 1;");
        } else {
            asm volatile("cp.async.wait_group 0;");
        }
        __syncthreads();

        uint32_t ah[4][4], al[4][4];
        #pragma unroll
        for (int mf = 0; mf < 4; mf++) {
            int r = wm0 + mf * 16;
            int i0 = buf * BF_TILE + (r + gid) * BF_STRIDE + 2 * tig;
            int i1 = buf * BF_TILE + (r + gid + 8) * BF_STRIDE + 2 * tig;
            ah[mf][0] = *(const uint32_t*)&smb[OFF_ABH + i0];
            ah[mf][1] = *(const uint32_t*)&smb[OFF_ABH + i1];
            ah[mf][2] = *(const uint32_t*)&smb[OFF_ABH + i0 + 8];
            ah[mf][3] = *(const uint32_t*)&smb[OFF_ABH + i1 + 8];
            al[mf][0] = *(const uint32_t*)&smb[OFF_ABL + i0];
            al[mf][1] = *(const uint32_t*)&smb[OFF_ABL + i1];
            al[mf][2] = *(const uint32_t*)&smb[OFF_ABL + i0 + 8];
            al[mf][3] = *(const uint32_t*)&smb[OFF_ABL + i1 + 8];
        }
        uint32_t bh[4][2], bl[4][2];
        #pragma unroll
        for (int nf = 0; nf < 4; nf++) {
            int cN = wn0 + nf * 8 + gid;
            int j0 = buf * BF_TILE + cN * BF_STRIDE + 2 * tig;
            bh[nf][0] = *(const uint32_t*)&smb[OFF_BBH + j0];
            bh[nf][1] = *(const uint32_t*)&smb[OFF_BBH + j0 + 8];
            bl[nf][0] = *(const uint32_t*)&smb[OFF_BBL + j0];
            bl[nf][1] = *(const uint32_t*)&smb[OFF_BBL + j0 + 8];
        }
        #pragma unroll
        for (int mf = 0; mf < 4; mf++)
            #pragma unroll
            for (int nf = 0; nf < 4; nf++) {
                mma_bf16(acc[mf][nf], ah[mf][0], ah[mf][1], ah[mf][2], ah[mf][3],
                         bh[nf][0], bh[nf][1]);
                mma_bf16(acc[mf][nf], al[mf][0], al[mf][1], al[mf][2], al[mf][3],
                         bh[nf][0], bh[nf][1]);
                mma_bf16(acc[mf][nf], ah[mf][0], ah[mf][1], ah[mf][2], ah[mf][3],
                         bl[nf][0], bl[nf][1]);
            }
        __syncthreads();
    }

    #pragma unroll
    for (int mf = 0; mf < 4; mf++) {
        #pragma unroll
        for (int nf = 0; nf < 4; nf++) {
            int r0 = m0 + wm0 + mf * 16 + gid;
            int cN = n0 + wn0 + nf * 8 + 2 * tig;
            float2 bv = *(const float2*)(bias + cN);
            float2 o0 = make_float2(acc[mf][nf][0] + bv.x, acc[mf][nf][1] + bv.y);
            float2 o1 = make_float2(acc[mf][nf][2] + bv.x, acc[mf][nf][3] + bv.y);
            *(float2*)(C + (size_t)r0 * DQ + cN) = o0;
            *(float2*)(C + (size_t)(r0 + 8) * DQ + cN) = o1;
        }
    }
}

// ---------------- persistent scan kernel (bf16 mma, per-warp producer flags) --
// 128 CTAs x 256 threads; CTA owns 8 output columns. Sync: warp w reads only
// k in [128w,128w+128) = columns from producer CTAs [16w,16w+16). Each warp
// acquire-polls just those 16 flags (one L2 hop, skew-absorbing) instead of a
// global two-phase barrier. Producer publishes its flag with st.release after
// a __syncthreads that covers its cbnext stores. Double-buffer safety: a CTA
// reaches the write of buffer[t&1] (step t+1's update) only after its 8 warps
// collectively saw ALL 128 flags >= t+1, i.e. every CTA finished reading step
// t. fp32 c carried in registers; g_chand is the scan-to-scan handoff.
// SMEM: Bs 64 mma * 2 nf * 32 lanes * 8B = 32 KB, partials 32 KB
#define SCAN_SMEM_BYTES (32768 + 32768)

__global__ __launch_bounds__(256) void scan_kernel(
    const float* __restrict__ x,  const float* __restrict__ xi,
    const float* __restrict__ xf, const float* __restrict__ xc,
    const float* __restrict__ Wic, const float* __restrict__ Wfc,
    float* __restrict__ chand,             // [BQ*DQ] fp32 handoff
    __nv_bfloat16* __restrict__ cbf,       // [2][BQ*DQ] bf16 shadow
    float* __restrict__ h, int reverse, int epoch)
{
    extern __shared__ __align__(16) char smem_raw[];
    uint2* Bs   = (uint2*)smem_raw;                  // [64 mma][2 nf][32 lanes]
    float* part = (float*)(smem_raw + 32768);        // [8 warps][64 b][16 cols]

    const int tid  = threadIdx.x;
    const int lane = tid & 31;
    const int w    = tid >> 5;
    const int gid  = lane >> 2;       // groupID 0..7
    const int tig  = lane & 3;        // threadID in group
    const int n0   = blockIdx.x * 8;  // this CTA's output column base
    const int bid  = blockIdx.x;

    // ---- pre-lay weights bf16 in fragment order (once per scan) ----
    for (int idx = tid; idx < 64 * 2 * 32; idx += 256) {
        int l    = idx & 31;
        int nf   = (idx >> 5) & 1;
        int mi   = idx >> 6;
        int s    = mi >> 1;
        int half = mi & 1;
        int k0   = 32 * s + 8 * (l & 3) + 4 * half;
        int col  = n0 + (l >> 2);
        const float* M = nf ? Wfc : Wic;
        uint2 v;
        v.x = pack_bf16x2(M[(size_t)(k0 + 0) * DQ + col], M[(size_t)(k0 + 1) * DQ + col]);
        v.y = pack_bf16x2(M[(size_t)(k0 + 2) * DQ + col], M[(size_t)(k0 + 3) * DQ + col]);
        Bs[idx] = v;
    }
    __syncthreads();

    // tail addressing: 2 reps x 256 threads cover 64 b x 8 n cell updates;
    // fp32 c carried in registers across all steps.
    int bbs[2], gns[2];
    float t_c[2];
    #pragma unroll
    for (int rep = 0; rep < 2; rep++) {
        int rr = tid + rep * 256;
        bbs[rep] = rr >> 3;
        gns[rep] = n0 + (rr & 7);
        t_c[rep] = chand[(size_t)bbs[rep] * DQ + gns[rep]];   // initial c
    }

    // this warp's producer flag (lanes 0..15 poll 16 flags)
    const unsigned* myflag = g_flags + 16 * w + (lane & 15);

    for (int step = 0; step < LQ; step++) {
        const int t = reverse ? (LQ - 1 - step) : step;
        const __nv_bfloat16* cbprev = cbf + (step & 1) * (BQ * DQ);
        __nv_bfloat16* cbnext = cbf + ((step + 1) & 1) * (BQ * DQ);

        // ---- prefetch tail operands early (hidden under poll + mma phase) ----
        float t_xi[2], t_xf[2], t_xc[2], t_x[2];
        size_t offs[2];
        #pragma unroll
        for (int rep = 0; rep < 2; rep++) {
            size_t off = ((size_t)t * BQ + bbs[rep]) * DQ + gns[rep];
            offs[rep] = off;
            t_xi[rep] = __ldcg(xi + off);
            t_xf[rep] = __ldcg(xf + off);
            t_xc[rep] = __ldcg(xc + off);
            t_x[rep]  = __ldcg(x + off);
        }

        // ---- per-warp producer wait: acquire-poll this warp's 16 producers ----
        {
            const unsigned need = (unsigned)(epoch + step);
            if (lane < 16) {
                unsigned v;
                do {
                    asm volatile("ld.acquire.gpu.global.u32 %0, [%1];"
                                 : "=r"(v) : "l"(myflag) : "memory");
                } while (v < need);
            }
            __syncwarp();
        }

        float acc[4][2][4];
        #pragma unroll
        for (int m = 0; m < 4; m++)
            #pragma unroll
            for (int nf = 0; nf < 2; nf++)
                #pragma unroll
                for (int r = 0; r < 4; r++) acc[m][nf][r] = 0.f;

        #pragma unroll
        for (int j = 0; j < 4; j++) {
            int s = 4 * w + j;
            uint2 bu0 = Bs[((2 * s + 0) * 2 + 0) * 32 + lane];
            uint2 bv0 = Bs[((2 * s + 0) * 2 + 1) * 32 + lane];
            uint2 bu1 = Bs[((2 * s + 1) * 2 + 0) * 32 + lane];
            uint2 bv1 = Bs[((2 * s + 1) * 2 + 1) * 32 + lane];
            const __nv_bfloat16* abase = cbprev + (size_t)gid * DQ + 32 * s + 8 * tig;
            uint4 av[8];
            #pragma unroll
            for (int m = 0; m < 4; m++) {
                av[2 * m]     = __ldcg((const uint4*)(abase + (size_t)(m * 16) * DQ));
                av[2 * m + 1] = __ldcg((const uint4*)(abase + (size_t)(m * 16 + 8) * DQ));
            }
            #pragma unroll
            for (int m = 0; m < 4; m++) {
                mma_bf16(acc[m][0], av[2*m].x, av[2*m+1].x, av[2*m].y, av[2*m+1].y,
                         bu0.x, bu0.y);
                mma_bf16(acc[m][1], av[2*m].x, av[2*m+1].x, av[2*m].y, av[2*m+1].y,
                         bv0.x, bv0.y);
                mma_bf16(acc[m][0], av[2*m].z, av[2*m+1].z, av[2*m].w, av[2*m+1].w,
                         bu1.x, bu1.y);
                mma_bf16(acc[m][1], av[2*m].z, av[2*m+1].z, av[2*m].w, av[2*m+1].w,
                         bv1.x, bv1.y);
            }
        }

        // ---- write split-K partials: part[w][b][col] ----
        #pragma unroll
        for (int m = 0; m < 4; m++) {
            #pragma unroll
            for (int nf = 0; nf < 2; nf++) {
                int col = nf * 8 + 2 * tig;
                int b0r = m * 16 + gid;
                float2* p0 = (float2*)&part[((w * 64) + b0r) * 16 + col];
                float2* p1 = (float2*)&part[((w * 64) + b0r + 8) * 16 + col];
                *p0 = make_float2(acc[m][nf][0], acc[m][nf][1]);
                *p1 = make_float2(acc[m][nf][2], acc[m][nf][3]);
            }
        }
        __syncthreads();

        // ---- reduce over warps + elementwise update: 64b x 8n, 2 per thread ----
        #pragma unroll
        for (int rep = 0; rep < 2; rep++) {
            int rr = tid + rep * 256;
            int bb = rr >> 3, nn = rr & 7;
            float uu = 0.f, vv = 0.f;
            #pragma unroll
            for (int ww = 0; ww < 8; ww++) {
                uu += part[((ww * 64) + bb) * 16 + nn];
                vv += part[((ww * 64) + bb) * 16 + 8 + nn];
            }
            float iv = 1.0f / (1.0f + expf(-(t_xi[rep] + uu)));
            float fv = 1.0f / (1.0f + expf(-(t_xf[rep] + vv)));
            float cn = iv * t_xc[rep] + fv * t_c[rep];
            t_c[rep] = cn;                                       // register carry
            cbnext[(size_t)bb * DQ + gns[rep]] = __float2bfloat16_rn(cn);
            h[offs[rep]] = tanhf(cn) + t_x[rep];
        }

        // ---- publish: all cbnext stores done -> release own flag ----
        __syncthreads();
        if (tid == 0) {
            const unsigned val = (unsigned)(epoch + step + 1);
            asm volatile("st.release.gpu.global.u32 [%0], %1;"
                         :: "l"(g_flags + bid), "r"(val) : "memory");
        }
    }

    // ---- final c handoff for the next scan ----
    #pragma unroll
    for (int rep = 0; rep < 2; rep++)
        chand[(size_t)bbs[rep] * DQ + gns[rep]] = t_c[rep];
}

// ---------------- launcher ----------------
extern "C" void kernel_launch(void* const* d_in, const int* in_sizes, int n_in,
                              void* d_out, int out_size)
{
    (void)in_sizes; (void)n_in; (void)out_size;

    cudaFuncSetAttribute(scan_kernel, cudaFuncAttributeMaxDynamicSharedMemorySize,
                         SCAN_SMEM_BYTES);
    cudaFuncSetAttribute(sgemm_bf16x2, cudaFuncAttributeMaxDynamicSharedMemorySize,
                         GEMM_SMEM_BYTES);

    const int*   xs  = (const int*)d_in[0];
    const float* emb = (const float*)d_in[1];
    const float* P[16];
    for (int i = 0; i < 16; i++) P[i] = (const float*)d_in[2 + i];
    // P: 0=fw_Wix 1=fw_Wic 2=fw_Wfx 3=fw_Wfc 4=fw_Wcx 5=fw_bi 6=fw_bf 7=fw_bc
    //    8=bw_Wix 9=bw_Wic 10=bw_Wfx 11=bw_Wfc 12=bw_Wcx 13=bw_bi 14=bw_bf 15=bw_bc

    float *px, *ph, *pxi, *pxf, *pxc, *pch;
    __nv_bfloat16 *pcbf, *pabh, *pabl, *pwth, *pwtl;
    unsigned* pflags;
    cudaGetSymbolAddress((void**)&px,    g_x);
    cudaGetSymbolAddress((void**)&ph,    g_h);
    cudaGetSymbolAddress((void**)&pxi,   g_xi);
    cudaGetSymbolAddress((void**)&pxf,   g_xf);
    cudaGetSymbolAddress((void**)&pxc,   g_xc);
    cudaGetSymbolAddress((void**)&pch,   g_chand);
    cudaGetSymbolAddress((void**)&pcbf,  g_cbf);
    cudaGetSymbolAddress((void**)&pabh,  g_abh);
    cudaGetSymbolAddress((void**)&pabl,  g_abl);
    cudaGetSymbolAddress((void**)&pwth,  g_wth);
    cudaGetSymbolAddress((void**)&pwtl,  g_wtl);
    cudaGetSymbolAddress((void**)&pflags, g_flags);
    float* out = (float*)d_out;

    embed_kernel<<<MQ * DQ / 4 / 256, 256>>>(xs, emb, px);
    zero_kernel<<<(BQ * DQ + 255) / 256, 256>>>(pch, BQ * DQ);
    zero_kernel<<<(BQ * DQ + 255) / 256, 256>>>((float*)pcbf, BQ * DQ); // 2*BQ*DQ bf16
    zero_kernel<<<1, 256>>>((float*)pflags, NB_SCAN);

    // pre-split + transpose the 6 input-projection weight matrices (once)
    const int widx[6] = {0, 2, 4, 8, 10, 12};   // Wix, Wfx, Wcx for fw then bw
    dim3 tgrid(DQ / 32, DQ / 32), tblk(32, 8);
    for (int j = 0; j < 6; j++) {
        wsplit_t_kernel<<<tgrid, tblk>>>(P[widx[j]],
                                         pwth + (size_t)j * DQ * DQ,
                                         pwtl + (size_t)j * DQ * DQ);
    }

    const int AN4 = MQ * DQ / 4;                // 4M
    dim3 ggrid(DQ / TBN, MQ / TBM);             // (8, 128)
    for (int layer = 0; layer < 2; layer++) {
        // forward direction
        asplit_kernel<<<AN4 / 256, 256>>>((const float4*)px, (uint2*)pabh, (uint2*)pabl, AN4);
        sgemm_bf16x2<<<ggrid, 256, GEMM_SMEM_BYTES>>>(pabh, pabl,
            pwth + 0 * (size_t)DQ * DQ, pwtl + 0 * (size_t)DQ * DQ, P[5], pxi);
        sgemm_bf16x2<<<ggrid, 256, GEMM_SMEM_BYTES>>>(pabh, pabl,
            pwth + 1 * (size_t)DQ * DQ, pwtl + 1 * (size_t)DQ * DQ, P[6], pxf);
        sgemm_bf16x2<<<ggrid, 256, GEMM_SMEM_BYTES>>>(pabh, pabl,
            pwth + 2 * (size_t)DQ * DQ, pwtl + 2 * (size_t)DQ * DQ, P[7], pxc);
        scan_kernel<<<NB_SCAN, 256, SCAN_SMEM_BYTES>>>(px, pxi, pxf, pxc,
            P[1], P[3], pch, pcbf, ph, 0, (layer * 2 + 0) * LQ);
        // backward direction
        asplit_kernel<<<AN4 / 256, 256>>>((const float4*)ph, (uint2*)pabh, (uint2*)pabl, AN4);
        sgemm_bf16x2<<<ggrid, 256, GEMM_SMEM_BYTES>>>(pabh, pabl,
            pwth + 3 * (size_t)DQ * DQ, pwtl + 3 * (size_t)DQ * DQ, P[13], pxi);
        sgemm_bf16x2<<<ggrid, 256, GEMM_SMEM_BYTES>>>(pabh, pabl,
            pwth + 4 * (size_t)DQ * DQ, pwtl + 4 * (size_t)DQ * DQ, P[14], pxf);
        sgemm_bf16x2<<<ggrid, 256, GEMM_SMEM_BYTES>>>(pabh, pabl,
            pwth + 5 * (size_t)DQ * DQ, pwtl + 5 * (size_t)DQ * DQ, P[15], pxc);
        float* ho = (layer == 1) ? out : px;
        scan_kernel<<<NB_SCAN, 256, SCAN_SMEM_BYTES>>>(ph, pxi, pxf, pxc,
            P[9], P[11], pch, pcbf, ho, 1, (layer * 2 + 1) * LQ);
    }
}